// round 3
// baseline (speedup 1.0000x reference)
#include <cuda_runtime.h>
#include <math.h>

// Problem constants (fixed by the reference)
#define B_  1024
#define T_  80
#define E_  512
#define U_  512
#define M1  (B_ * T_)   // 81920 rows of the input-projection GEMM

// Static device scratch (allocation-free rule: __device__ globals)
__device__ float g_xk[(size_t)M1 * U_];        // [B*T, U] input projection (+bias)
__device__ float g_h[2][(size_t)B_ * U_];      // ping-pong hidden state

// ---------------------------------------------------------------------------
// Kernel 1: g_xk[m, n] = sum_e emb[tokens[m], e] * W[e, n] + bias[n]
// BM=128, BN=64, BK=16, 256 threads, 8x4 micro-tile, float4 LDG/LDS/STG.
// ---------------------------------------------------------------------------
__global__ void __launch_bounds__(256)
gemm_embed_kernel(const int* __restrict__ tokens,
                  const float* __restrict__ emb,
                  const float* __restrict__ W,
                  const float* __restrict__ bias)
{
    constexpr int BM = 128;
    constexpr int TM = 8;

    __shared__ __align__(16) float As[16][BM + 4];  // transposed: As[k][m]
    __shared__ __align__(16) float Bs[16][64 + 4];
    __shared__ int rows[BM];

    const int tid = threadIdx.x;
    const int m0 = blockIdx.x * BM;
    const int n0 = blockIdx.y * 64;

    for (int i = tid; i < BM; i += 256) rows[i] = tokens[m0 + i];
    __syncthreads();

    const int tx = tid & 15;        // n-direction, 4 cols each
    const int ty = tid >> 4;        // m-direction, TM rows each

    float acc[TM][4];
#pragma unroll
    for (int i = 0; i < TM; i++)
#pragma unroll
        for (int j = 0; j < 4; j++) acc[i][j] = 0.f;

    const int lb = tid >> 4;          // B tile: row 0..15
    const int lc = (tid & 15) << 2;   // B tile: col group

    for (int k0 = 0; k0 < E_; k0 += 16) {
        // Load to registers (overlaps previous tile's compute)
        float4 av[BM / 64];           // BM*16/(256*4) float4 per thread
#pragma unroll
        for (int u = 0; u < BM / 64; u++) {
            int f = tid + u * 256;
            int r = f >> 2, ck = (f & 3) << 2;
            av[u] = *reinterpret_cast<const float4*>(
                emb + (size_t)rows[r] * E_ + k0 + ck);
        }
        float4 bv = *reinterpret_cast<const float4*>(
            W + (size_t)(k0 + lb) * U_ + n0 + lc);

        __syncthreads();
#pragma unroll
        for (int u = 0; u < BM / 64; u++) {
            int f = tid + u * 256;
            int r = f >> 2, ck = (f & 3) << 2;
            As[ck + 0][r] = av[u].x; As[ck + 1][r] = av[u].y;
            As[ck + 2][r] = av[u].z; As[ck + 3][r] = av[u].w;
        }
        *reinterpret_cast<float4*>(&Bs[lb][lc]) = bv;
        __syncthreads();

#pragma unroll
        for (int kk = 0; kk < 16; kk++) {
            float4 bq = *reinterpret_cast<float4*>(&Bs[kk][tx << 2]);
            float bw[4] = {bq.x, bq.y, bq.z, bq.w};
#pragma unroll
            for (int i4 = 0; i4 < TM; i4 += 4) {
                float4 aq = *reinterpret_cast<float4*>(&As[kk][ty * TM + i4]);
                float aw[4] = {aq.x, aq.y, aq.z, aq.w};
#pragma unroll
                for (int ii = 0; ii < 4; ii++)
#pragma unroll
                    for (int j = 0; j < 4; j++)
                        acc[i4 + ii][j] = fmaf(aw[ii], bw[j], acc[i4 + ii][j]);
            }
        }
    }

    // Epilogue: add bias, store fp32
    float4 b4 = *reinterpret_cast<const float4*>(bias + n0 + (tx << 2));
#pragma unroll
    for (int i = 0; i < TM; i++) {
        size_t row = (size_t)(m0 + ty * TM + i);
        float4 o;
        o.x = acc[i][0] + b4.x;
        o.y = acc[i][1] + b4.y;
        o.z = acc[i][2] + b4.z;
        o.w = acc[i][3] + b4.w;
        *reinterpret_cast<float4*>(g_xk + row * U_ + n0 + (tx << 2)) = o;
    }
}

// ---------------------------------------------------------------------------
// First step: h0 = 0  ->  h1 = tanh(xk[:, 0, :])
// ---------------------------------------------------------------------------
__global__ void first_step_kernel()
{
    int i = blockIdx.x * blockDim.x + threadIdx.x;
    if (i < B_ * U_) {
        int b = i / U_, u = i - b * U_;
        g_h[1][i] = tanhf(g_xk[((size_t)b * T_ + 0) * U_ + u]);
    }
}

// ---------------------------------------------------------------------------
// RNN step t (t>=1): g_h[cur^1] = tanh(xk[:, t, :] + g_h[cur] @ R)
// BM=64, BN=64, BK=16, 256 threads, 4x4 micro-tile. Grid = 16x8 = 128 CTAs.
// ---------------------------------------------------------------------------
__global__ void __launch_bounds__(256)
rnn_step_kernel(const float* __restrict__ R, int t, int cur)
{
    constexpr int BM = 64;
    constexpr int TM = 4;

    __shared__ __align__(16) float As[16][BM + 4];  // As[k][m]
    __shared__ __align__(16) float Bs[16][64 + 4];

    const int tid = threadIdx.x;
    const int m0 = blockIdx.x * BM;
    const int n0 = blockIdx.y * 64;

    const float* __restrict__ H = g_h[cur];
    float* __restrict__ Hn = g_h[cur ^ 1];

    const int tx = tid & 15;
    const int ty = tid >> 4;

    float acc[TM][4];
#pragma unroll
    for (int i = 0; i < TM; i++)
#pragma unroll
        for (int j = 0; j < 4; j++) acc[i][j] = 0.f;

    const int la = tid >> 2;          // A tile: row 0..63
    const int lk = (tid & 3) << 2;    // A tile: k group
    const int lb = tid >> 4;
    const int lc = (tid & 15) << 2;

    for (int k0 = 0; k0 < U_; k0 += 16) {
        float4 av = *reinterpret_cast<const float4*>(
            H + (size_t)(m0 + la) * U_ + k0 + lk);
        float4 bv = *reinterpret_cast<const float4*>(
            R + (size_t)(k0 + lb) * U_ + n0 + lc);

        __syncthreads();
        As[lk + 0][la] = av.x; As[lk + 1][la] = av.y;
        As[lk + 2][la] = av.z; As[lk + 3][la] = av.w;
        *reinterpret_cast<float4*>(&Bs[lb][lc]) = bv;
        __syncthreads();

#pragma unroll
        for (int kk = 0; kk < 16; kk++) {
            float4 bq = *reinterpret_cast<float4*>(&Bs[kk][tx << 2]);
            float bw[4] = {bq.x, bq.y, bq.z, bq.w};
            float4 aq = *reinterpret_cast<float4*>(&As[kk][ty * TM]);
            float aw[4] = {aq.x, aq.y, aq.z, aq.w};
#pragma unroll
            for (int ii = 0; ii < 4; ii++)
#pragma unroll
                for (int j = 0; j < 4; j++)
                    acc[ii][j] = fmaf(aw[ii], bw[j], acc[ii][j]);
        }
    }

    // Epilogue: + xk[:, t, :], tanh, store next h
#pragma unroll
    for (int i = 0; i < TM; i++) {
        size_t b = (size_t)(m0 + ty * TM + i);
        float4 xv = *reinterpret_cast<const float4*>(
            g_xk + (b * T_ + t) * U_ + n0 + (tx << 2));
        float4 o;
        o.x = tanhf(acc[i][0] + xv.x);
        o.y = tanhf(acc[i][1] + xv.y);
        o.z = tanhf(acc[i][2] + xv.z);
        o.w = tanhf(acc[i][3] + xv.w);
        *reinterpret_cast<float4*>(Hn + b * U_ + n0 + (tx << 2)) = o;
    }
}

// ---------------------------------------------------------------------------
// Final: out[b] = sigmoid(h[b] . fc_w + fc_b)   (one warp per row)
// ---------------------------------------------------------------------------
__global__ void final_kernel(const float* __restrict__ fc_w,
                             const float* __restrict__ fc_b,
                             float* __restrict__ out,
                             int hbuf)
{
    int gw = (blockIdx.x * blockDim.x + threadIdx.x) >> 5;
    int lane = threadIdx.x & 31;
    if (gw >= B_) return;
    const float* h = g_h[hbuf] + (size_t)gw * U_;
    float s = 0.f;
    for (int i = lane; i < U_; i += 32) s = fmaf(h[i], fc_w[i], s);
#pragma unroll
    for (int o = 16; o; o >>= 1) s += __shfl_xor_sync(0xffffffffu, s, o);
    if (lane == 0) out[gw] = 1.f / (1.f + expf(-(s + fc_b[0])));
}

// ---------------------------------------------------------------------------
// Launch
// ---------------------------------------------------------------------------
extern "C" void kernel_launch(void* const* d_in, const int* in_sizes, int n_in,
                              void* d_out, int out_size)
{
    const int*   tokens     = (const int*)  d_in[0];   // [B, T]
    const float* emb        = (const float*)d_in[1];   // [V, E]
    const float* kernel     = (const float*)d_in[2];   // [E, U]
    const float* rec_kernel = (const float*)d_in[3];   // [U, U]
    const float* bias       = (const float*)d_in[4];   // [U]
    const float* fc_w       = (const float*)d_in[5];   // [U, 1]
    const float* fc_b       = (const float*)d_in[6];   // [1]
    float* out = (float*)d_out;                        // [B, 1]

    // 1) Input projection for all timesteps (one big GEMM, gather fused)
    dim3 g1(M1 / 128, U_ / 64);   // (640, 8)
    gemm_embed_kernel<<<g1, 256>>>(tokens, emb, kernel, bias);

    // 2) t = 0: h = tanh(xk_0)   (h0 == 0, GEMM skipped)
    first_step_kernel<<<(B_ * U_ + 255) / 256, 256>>>();

    // 3) t = 1..79: sequential recurrence (ping-pong buffers)
    dim3 g2(B_ / 64, U_ / 64);    // (16, 8) = 128 CTAs
    int cur = 1;
    for (int t = 1; t < T_; t++) {
        rnn_step_kernel<<<g2, 256>>>(rec_kernel, t, cur);
        cur ^= 1;
    }
    // After 79 flips starting at 1 -> final h lives in g_h[cur] == g_h[0]

    // 4) Classifier head + sigmoid
    final_kernel<<<B_ / 8, 256>>>(fc_w, fc_b, out, cur);
}